// round 15
// baseline (speedup 1.0000x reference)
#include <cuda_runtime.h>
#include <cuda_bf16.h>
#include <cuda_fp16.h>
#include <cstdint>

#define Nn 4096
#define IND 512
#define OD 512
#define Hh 8
#define Dd 64
#define ALPHA 0.2f
#define EPSV 1e-5f
#define LOG2E 1.4426950408889634f
#define ITILES 16
#define NTILES 32

__device__ __nv_bfloat16 g_xhi[Nn * IND], g_xlo[Nn * IND];
__device__ __nv_bfloat16 g_whi[OD * IND], g_wlo[OD * IND];
__device__ float g_Wh[Nn * OD];
__device__ __half g_Bf16[Nn * OD];                 // fp16(Wh), [i][o]
__device__ float g_sdL[Hh * Nn], g_ssL[Hh * Nn];   // scores * log2(e)
__device__ unsigned g_mask[Nn * (Nn / 32)];
__device__ float g_hp[Nn * OD];
__device__ float g_cs[ITILES * OD], g_cq[ITILES * OD];
__device__ float g_mean[OD], g_rstd[OD];

__device__ __forceinline__ unsigned bfpack(float hi, float lo) {
    unsigned r;
    asm("cvt.rn.bf16x2.f32 %0, %1, %2;" : "=r"(r) : "f"(hi), "f"(lo));
    return r;
}
__device__ __forceinline__ float lowf(unsigned u) { return __uint_as_float(u << 16); }
__device__ __forceinline__ float hif(unsigned u) { return __uint_as_float(u & 0xffff0000u); }
__device__ __forceinline__ float ex2f(float x) {
    float r;
    asm("ex2.approx.ftz.f32 %0, %1;" : "=f"(r) : "f"(x));
    return r;
}
__device__ __forceinline__ uint32_t smem_u32(const void* p) {
    uint32_t a;
    asm("{ .reg .u64 t; cvta.to.shared.u64 t, %1; cvt.u32.u64 %0, t; }" : "=r"(a) : "l"(p));
    return a;
}
__device__ __forceinline__ float pfun(float tL, unsigned bit) {
    float g = fmaxf(tL, ALPHA * tL);
    float p = ex2f(g);
    return bit ? p : 0.f;
}
__device__ __forceinline__ unsigned hpack2n(float vlo, float vhi) {
    __half2 h = __floats2half2_rn(vlo, vhi);
    return reinterpret_cast<unsigned&>(h);
}

#define MMA(cc, A0, A1, A2, A3, B0, B1)                                            \
    asm volatile("mma.sync.aligned.m16n8k16.row.col.f32.bf16.bf16.f32 "            \
                 "{%0,%1,%2,%3},{%4,%5,%6,%7},{%8,%9},{%0,%1,%2,%3};"              \
                 : "+f"(cc[0]), "+f"(cc[1]), "+f"(cc[2]), "+f"(cc[3])              \
                 : "r"(A0), "r"(A1), "r"(A2), "r"(A3), "r"(B0), "r"(B1))

#define MMA16(cc, A0, A1, A2, A3, B0, B1)                                          \
    asm volatile("mma.sync.aligned.m16n8k16.row.col.f32.f16.f16.f32 "              \
                 "{%0,%1,%2,%3},{%4,%5,%6,%7},{%8,%9},{%0,%1,%2,%3};"              \
                 : "+f"(cc[0]), "+f"(cc[1]), "+f"(cc[2]), "+f"(cc[3])              \
                 : "r"(A0), "r"(A1), "r"(A2), "r"(A3), "r"(B0), "r"(B1))

#define LDMX4T(r0, r1, r2, r3, addr)                                               \
    asm volatile("ldmatrix.sync.aligned.m8n8.x4.trans.shared.b16 {%0,%1,%2,%3},[%4];" \
                 : "=r"(r0), "=r"(r1), "=r"(r2), "=r"(r3) : "r"(addr))

#define LDMX4(r0, r1, r2, r3, addr)                                                \
    asm volatile("ldmatrix.sync.aligned.m8n8.x4.shared.b16 {%0,%1,%2,%3},[%4];"    \
                 : "=r"(r0), "=r"(r1), "=r"(r2), "=r"(r3) : "r"(addr))

#define CPA16(dst, src)                                                            \
    asm volatile("cp.async.cg.shared.global [%0], [%1], 16;" :: "r"(dst), "l"(src) : "memory")
#define CPCOMMIT() asm volatile("cp.async.commit_group;" ::: "memory")
#define CPWAIT(N) asm volatile("cp.async.wait_group %0;" :: "n"(N) : "memory")

// ================= Kernel P: fp32 -> bf16 hi/lo convert =================
__global__ void __launch_bounds__(256) cvt_kernel(const float* __restrict__ src,
                                                  __nv_bfloat16* __restrict__ hi,
                                                  __nv_bfloat16* __restrict__ lo) {
    const int i4 = (blockIdx.x * 256 + threadIdx.x) * 4;
    float4 v = *(const float4*)&src[i4];
    unsigned h01 = bfpack(v.y, v.x), h23 = bfpack(v.w, v.z);
    unsigned l01 = bfpack(v.y - hif(h01), v.x - lowf(h01));
    unsigned l23 = bfpack(v.w - hif(h23), v.z - lowf(h23));
    *(uint2*)&hi[i4] = make_uint2(h01, h23);
    *(uint2*)&lo[i4] = make_uint2(l01, l23);
}

// ================= Kernel A: UNION = gemm (blocks 0..255) + maskpack (blocks 256..767) =================
#define GXHI 0
#define GXLO 16384
#define GWHI 32768
#define GWLO 40960
#define GBUF 49152
#define SMEM_GEMM (2 * GBUF)

__device__ __forceinline__ void gemm_issue(uint32_t smb, int buf, int i0, int o0, int k0, int t) {
    const uint32_t bb = smb + (unsigned)buf * GBUF;
#pragma unroll
    for (int q = 0; q < 4; q++) {
        int idx = t + q * 256;
        int i = idx >> 3, cc = idx & 7;
        unsigned so = (unsigned)i * 128u + (unsigned)((cc ^ (i & 7)) << 4);
        const size_t gof = (size_t)(i0 + i) * IND + k0 + cc * 8;
        CPA16(bb + GXHI + so, &g_xhi[gof]);
        CPA16(bb + GXLO + so, &g_xlo[gof]);
    }
#pragma unroll
    for (int q = 0; q < 2; q++) {
        int idx = t + q * 256;
        int o = idx >> 3, cc = idx & 7;
        unsigned so = (unsigned)o * 128u + (unsigned)((cc ^ (o & 7)) << 4);
        const size_t gof = (size_t)(o0 + o) * IND + k0 + cc * 8;
        CPA16(bb + GWHI + so, &g_whi[gof]);
        CPA16(bb + GWLO + so, &g_wlo[gof]);
    }
}

__device__ void gemm_body(char* dsm, int bx) {
    const uint32_t smb = smem_u32(dsm);
    const int o0 = (bx & 7) * 64, i0 = (bx >> 3) * 128;
    const int t = threadIdx.x, w = t >> 5, lane = t & 31;
    const int l3 = lane & 3, l7 = lane & 7, l15 = lane & 15;

    float c[8][4];
#pragma unroll
    for (int nt = 0; nt < 8; nt++)
#pragma unroll
        for (int q = 0; q < 4; q++) c[nt][q] = 0.f;

    gemm_issue(smb, 0, i0, o0, 0, t);
    CPCOMMIT();

    for (int ch = 0; ch < 8; ch++) {
        if (ch < 7) {
            gemm_issue(smb, (ch + 1) & 1, i0, o0, (ch + 1) * 64, t);
            CPCOMMIT();
            CPWAIT(1);
        } else {
            CPWAIT(0);
        }
        __syncthreads();
        const uint32_t bb = smb + (unsigned)(ch & 1) * GBUF;

#pragma unroll
        for (int ks = 0; ks < 4; ks++) {
            uint32_t arow = bb + GXHI + (unsigned)(w * 16 + l15) * 128u +
                            (((unsigned)(2 * ks + (lane >> 4)) ^ (unsigned)l7) << 4);
            uint32_t ah0, ah1, ah2, ah3, al0, al1, al2, al3;
            LDMX4(ah0, ah1, ah2, ah3, arow);
            LDMX4(al0, al1, al2, al3, arow + 16384);
#pragma unroll
            for (int np = 0; np < 4; np++) {
                uint32_t brow = bb + GWHI +
                                (unsigned)(np * 16 + (lane >> 4) * 8 + l7) * 128u +
                                (((unsigned)(2 * ks + ((lane >> 3) & 1)) ^ (unsigned)l7) << 4);
                uint32_t bh0, bh1, bh2, bh3, bl0, bl1, bl2, bl3;
                LDMX4(bh0, bh1, bh2, bh3, brow);
                LDMX4(bl0, bl1, bl2, bl3, brow + 8192);
                MMA(c[2 * np], ah0, ah1, ah2, ah3, bh0, bh1);
                MMA(c[2 * np], al0, al1, al2, al3, bh0, bh1);
                MMA(c[2 * np], ah0, ah1, ah2, ah3, bl0, bl1);
                MMA(c[2 * np + 1], ah0, ah1, ah2, ah3, bh2, bh3);
                MMA(c[2 * np + 1], al0, al1, al2, al3, bh2, bh3);
                MMA(c[2 * np + 1], ah0, ah1, ah2, ah3, bl2, bl3);
            }
        }
        __syncthreads();
    }

    const int rA0 = w * 16 + (lane >> 2), rA1 = rA0 + 8;
#pragma unroll
    for (int nt = 0; nt < 8; nt++) {
        const int col = o0 + nt * 8 + l3 * 2;
        const size_t f0 = (size_t)(i0 + rA0) * OD + col;
        const size_t f1 = (size_t)(i0 + rA1) * OD + col;
        float v00 = c[nt][0], v01 = c[nt][1], v10 = c[nt][2], v11 = c[nt][3];
        *(float2*)&g_Wh[f0] = make_float2(v00, v01);
        *(float2*)&g_Wh[f1] = make_float2(v10, v11);
        *(unsigned*)&g_Bf16[f0] = hpack2n(v00, v01);
        *(unsigned*)&g_Bf16[f1] = hpack2n(v10, v11);
    }
}

// maskpack part: block handles 8 rows, warp-per-row, PROVEN bit layout:
// bit l of g_mask[row*128 + k]  <->  adj[row][k*32 + l]
__device__ void maskpack_body(const int* __restrict__ adj, int mb) {
    const int w = threadIdx.x >> 5, lane = threadIdx.x & 31;
    const int row = mb * 8 + w;
    const int* arow = adj + (size_t)row * Nn;
#pragma unroll 8
    for (int k = 0; k < 128; k++) {
        unsigned bal = __ballot_sync(0xffffffffu, arow[k * 32 + lane] > 0);
        if (lane == 0) g_mask[row * 128 + k] = bal;
    }
}

__global__ void __launch_bounds__(256, 2) gemm_mask_kernel(const int* __restrict__ adj) {
    extern __shared__ char dsm[];
    const int bx = blockIdx.x;
    if (bx < 256) {
        gemm_body(dsm, bx);
    } else {
        maskpack_body(adj, bx - 256);
    }
}

// ================= Kernel C: scores, warp-per-node =================
__global__ void __launch_bounds__(256) scores_kernel(const float* __restrict__ a) {
    const int w = threadIdx.x >> 5, lane = threadIdx.x & 31;
    const int j = blockIdx.x * 8 + w;
    const int h = lane >> 2, q = lane & 3;
    const float* wrow = &g_Wh[(size_t)j * OD + h * 64 + q * 16];
    float ss = 0.f, sd = 0.f;
#pragma unroll
    for (int d4 = 0; d4 < 4; d4++) {
        float4 wv = ((const float4*)wrow)[d4];
        float4 as = *(const float4*)&a[q * 16 + d4 * 4];
        float4 ad = *(const float4*)&a[64 + q * 16 + d4 * 4];
        ss += wv.x * as.x + wv.y * as.y + wv.z * as.z + wv.w * as.w;
        sd += wv.x * ad.x + wv.y * ad.y + wv.z * ad.z + wv.w * ad.w;
    }
    ss += __shfl_xor_sync(0xffffffffu, ss, 1);
    ss += __shfl_xor_sync(0xffffffffu, ss, 2);
    sd += __shfl_xor_sync(0xffffffffu, sd, 1);
    sd += __shfl_xor_sync(0xffffffffu, sd, 2);
    if (q == 0) {
        g_ssL[h * Nn + j] = ss * LOG2E;
        g_sdL[h * Nn + j] = sd * LOG2E;
    }
}

// ================= Kernel D: fp16 1-MMA attention, 32 rows/warp, 1 CTA/SM =================
#define MSK_O 16384
#define SSL_O 20480
#define BUFSZ 21504
#define COLS_O 43008
#define COLQ_O 45056
#define SMEM_ATTN 47104

struct PFrag {
    unsigned a0, a1, a2, a3;
};

__device__ __forceinline__ PFrag make_frag(const char* bpd, int kk, int r0, int r1,
                                           float sd0, float sd1, int l3,
                                           float& z0, float& z1) {
    const int jc = kk * 16 + l3 * 2;
    const float2 sA = *(const float2*)(bpd + SSL_O + jc * 4);
    const float2 sB = *(const float2*)(bpd + SSL_O + (jc + 8) * 4);
    const unsigned sh = (kk & 1) * 16 + l3 * 2;
    const unsigned mw0 = (*(const unsigned*)(bpd + MSK_O + r0 * 16 + ((kk >> 1) << 2))) >> sh;
    const unsigned mw1 = (*(const unsigned*)(bpd + MSK_O + r1 * 16 + ((kk >> 1) << 2))) >> sh;

    float p00 = pfun(sd0 + sA.x, mw0 & 1u);
    float p01 = pfun(sd0 + sA.y, mw0 & 2u);
    float p08 = pfun(sd0 + sB.x, (mw0 >> 8) & 1u);
    float p09 = pfun(sd0 + sB.y, (mw0 >> 8) & 2u);
    float p10 = pfun(sd1 + sA.x, mw1 & 1u);
    float p11 = pfun(sd1 + sA.y, mw1 & 2u);
    float p18 = pfun(sd1 + sB.x, (mw1 >> 8) & 1u);
    float p19 = pfun(sd1 + sB.y, (mw1 >> 8) & 2u);
    z0 += (p00 + p01) + (p08 + p09);
    z1 += (p10 + p11) + (p18 + p19);

    PFrag f;
    f.a0 = hpack2n(p00, p01);
    f.a1 = hpack2n(p10, p11);
    f.a2 = hpack2n(p08, p09);
    f.a3 = hpack2n(p18, p19);
    return f;
}

__device__ __forceinline__ void attn_issue(uint32_t smb, int b, int h, int i0, int j0, int t) {
    const uint32_t bb = smb + (unsigned)b * BUFSZ;
#pragma unroll
    for (int q = 0; q < 4; q++) {
        int idx = t + q * 256;
        int j = idx >> 3, cc = idx & 7;
        unsigned so = (unsigned)j * 128u + (unsigned)((cc ^ (j & 7)) << 4);
        CPA16(bb + so, &g_Bf16[(size_t)(j0 + j) * OD + h * 64 + cc * 8]);
    }
    CPA16(bb + MSK_O + t * 16, &g_mask[(size_t)(i0 + t) * 128 + (j0 >> 5)]);
    if (t < 32) CPA16(bb + SSL_O + t * 16, &g_ssL[h * Nn + j0 + t * 4]);
}

__global__ void __launch_bounds__(256, 1) attn_mma_kernel() {
    extern __shared__ char dsm[];
    const uint32_t smb = smem_u32(dsm);

    const int h = blockIdx.x, it = blockIdx.y, i0 = it * 256;
    const int t = threadIdx.x, w = t >> 5, lane = t & 31;
    const int l3 = lane & 3, l7 = lane & 7, l15 = lane & 15;
    const int rB = w * 32 + (lane >> 2);
    const float sd0 = g_sdL[h * Nn + i0 + rB];
    const float sd1 = g_sdL[h * Nn + i0 + rB + 8];
    const float sd2 = g_sdL[h * Nn + i0 + rB + 16];
    const float sd3 = g_sdL[h * Nn + i0 + rB + 24];

    float z0 = 0.f, z1 = 0.f, z2 = 0.f, z3 = 0.f;
    float c[2][8][4];
#pragma unroll
    for (int blk = 0; blk < 2; blk++)
#pragma unroll
        for (int nt = 0; nt < 8; nt++)
#pragma unroll
            for (int q = 0; q < 4; q++) c[blk][nt][q] = 0.f;

    attn_issue(smb, 0, h, i0, 0, t);
    CPCOMMIT();

    for (int tl = 0; tl < NTILES; tl++) {
        if (tl < NTILES - 1) {
            attn_issue(smb, (tl + 1) & 1, h, i0, (tl + 1) * 128, t);
            CPCOMMIT();
            CPWAIT(1);
        } else {
            CPWAIT(0);
        }
        __syncthreads();

        const uint32_t bb = smb + (unsigned)(tl & 1) * BUFSZ;
        const char* bpd = dsm + (tl & 1) * BUFSZ;

#pragma unroll
        for (int kk = 0; kk < 8; kk++) {
            PFrag f0 = make_frag(bpd, kk, rB, rB + 8, sd0, sd1, l3, z0, z1);
            PFrag f1 = make_frag(bpd, kk, rB + 16, rB + 24, sd2, sd3, l3, z2, z3);

            const unsigned rowoff = (unsigned)(kk * 16 + l15) * 128u;
#pragma unroll
            for (int np = 0; np < 4; np++) {
                const unsigned chn =
                    (((unsigned)(np * 2 + (lane >> 4)) ^ (unsigned)l7) << 4);
                uint32_t bh0, bh1, bh2, bh3;
                LDMX4T(bh0, bh1, bh2, bh3, bb + rowoff + chn);
                MMA16(c[0][2 * np], f0.a0, f0.a1, f0.a2, f0.a3, bh0, bh1);
                MMA16(c[1][2 * np], f1.a0, f1.a1, f1.a2, f1.a3, bh0, bh1);
                MMA16(c[0][2 * np + 1], f0.a0, f0.a1, f0.a2, f0.a3, bh2, bh3);
                MMA16(c[1][2 * np + 1], f1.a0, f1.a1, f1.a2, f1.a3, bh2, bh3);
            }
        }
        __syncthreads();
    }

#pragma unroll
    for (int d = 1; d <= 2; d <<= 1) {
        z0 += __shfl_xor_sync(0xffffffffu, z0, d);
        z1 += __shfl_xor_sync(0xffffffffu, z1, d);
        z2 += __shfl_xor_sync(0xffffffffu, z2, d);
        z3 += __shfl_xor_sync(0xffffffffu, z3, d);
    }
    const float inv[4] = {1.0f / z0, 1.0f / z1, 1.0f / z2, 1.0f / z3};

    float* colS = (float*)(dsm + COLS_O);
    float* colQ = (float*)(dsm + COLQ_O);

#pragma unroll
    for (int nt = 0; nt < 8; nt++) {
        float vv[4][2];
#pragma unroll
        for (int blk = 0; blk < 2; blk++) {
#pragma unroll
            for (int half = 0; half < 2; half++) {
                const int ri = blk * 2 + half;
                float va = c[blk][nt][2 * half] * inv[ri];
                float vb = c[blk][nt][2 * half + 1] * inv[ri];
                vv[ri][0] = va;
                vv[ri][1] = vb;
                const int row = rB + blk * 16 + half * 8;
                *(float2*)&g_hp[(size_t)(i0 + row) * OD + h * 64 + nt * 8 + l3 * 2] =
                    make_float2(va, vb);
            }
        }
        float s0 = vv[0][0] + vv[1][0] + vv[2][0] + vv[3][0];
        float s1 = vv[0][1] + vv[1][1] + vv[2][1] + vv[3][1];
        float q0 = vv[0][0] * vv[0][0] + vv[1][0] * vv[1][0] + vv[2][0] * vv[2][0] +
                   vv[3][0] * vv[3][0];
        float q1 = vv[0][1] * vv[0][1] + vv[1][1] * vv[1][1] + vv[2][1] * vv[2][1] +
                   vv[3][1] * vv[3][1];
#pragma unroll
        for (int d = 4; d < 32; d <<= 1) {
            s0 += __shfl_xor_sync(0xffffffffu, s0, d);
            s1 += __shfl_xor_sync(0xffffffffu, s1, d);
            q0 += __shfl_xor_sync(0xffffffffu, q0, d);
            q1 += __shfl_xor_sync(0xffffffffu, q1, d);
        }
        if (lane < 4) {
            colS[w * 64 + nt * 8 + lane * 2] = s0;
            colS[w * 64 + nt * 8 + lane * 2 + 1] = s1;
            colQ[w * 64 + nt * 8 + lane * 2] = q0;
            colQ[w * 64 + nt * 8 + lane * 2 + 1] = q1;
        }
    }
    __syncthreads();
    if (t < 64) {
        float s = 0.f, q = 0.f;
#pragma unroll
        for (int ww = 0; ww < 8; ww++) {
            s += colS[ww * 64 + t];
            q += colQ[ww * 64 + t];
        }
        g_cs[it * OD + h * 64 + t] = s;
        g_cq[it * OD + h * 64 + t] = q;
    }
}

// ================= Kernel E: column stats =================
__global__ void __launch_bounds__(1024) colstats_kernel() {
    const int w = threadIdx.x >> 5, lane = threadIdx.x & 31;
    const int col = blockIdx.x * 32 + w;
    float s = (lane < ITILES) ? g_cs[lane * OD + col] : 0.f;
    float q = (lane < ITILES) ? g_cq[lane * OD + col] : 0.f;
#pragma unroll
    for (int d = 16; d >= 1; d >>= 1) {
        s += __shfl_xor_sync(0xffffffffu, s, d);
        q += __shfl_xor_sync(0xffffffffu, q, d);
    }
    if (lane == 0) {
        float mean = s * (1.0f / Nn);
        float var = q * (1.0f / Nn) - mean * mean;
        g_mean[col] = mean;
        g_rstd[col] = rsqrtf(var + EPSV);
    }
}

// ================= Kernel F: layernorm + relu =================
__global__ void __launch_bounds__(256) norm_relu_kernel(const float* __restrict__ gamma,
                                                        const float* __restrict__ beta,
                                                        float* __restrict__ out) {
    const int base8 = (blockIdx.x * 256 + threadIdx.x) * 8;
#pragma unroll
    for (int half = 0; half < 2; half++) {
        const int basei = base8 + half * 4;
        const int col = basei & (OD - 1);
        float4 xv = *(const float4*)&g_hp[basei];
        float4 mn = *(const float4*)&g_mean[col];
        float4 rs = *(const float4*)&g_rstd[col];
        float4 ga = *(const float4*)&gamma[col];
        float4 be = *(const float4*)&beta[col];
        float4 o;
        o.x = fmaxf(0.f, ga.x * (xv.x - mn.x) * rs.x + be.x);
        o.y = fmaxf(0.f, ga.y * (xv.y - mn.y) * rs.y + be.y);
        o.z = fmaxf(0.f, ga.z * (xv.z - mn.z) * rs.z + be.z);
        o.w = fmaxf(0.f, ga.w * (xv.w - mn.w) * rs.w + be.w);
        *(float4*)&out[basei] = o;
    }
}

// ================= launch =================
extern "C" void kernel_launch(void* const* d_in, const int* in_sizes, int n_in,
                              void* d_out, int out_size) {
    const float* x     = (const float*)d_in[0];
    const int*   adj   = (const int*)d_in[1];
    const float* W     = (const float*)d_in[2];
    const float* a     = (const float*)d_in[3];
    const float* gamma = (const float*)d_in[4];
    const float* beta  = (const float*)d_in[5];
    float* out = (float*)d_out;

    static int attrs_set = 0;
    if (!attrs_set) {
        cudaFuncSetAttribute(attn_mma_kernel,
                             cudaFuncAttributeMaxDynamicSharedMemorySize, SMEM_ATTN);
        cudaFuncSetAttribute(gemm_mask_kernel,
                             cudaFuncAttributeMaxDynamicSharedMemorySize, SMEM_GEMM);
        attrs_set = 1;
    }

    __nv_bfloat16 *xhi, *xlo, *whi, *wlo;
    cudaGetSymbolAddress((void**)&xhi, g_xhi);
    cudaGetSymbolAddress((void**)&xlo, g_xlo);
    cudaGetSymbolAddress((void**)&whi, g_whi);
    cudaGetSymbolAddress((void**)&wlo, g_wlo);

    cvt_kernel<<<(Nn * IND / 4) / 256, 256>>>(x, xhi, xlo);
    cvt_kernel<<<(OD * IND / 4) / 256, 256>>>(W, whi, wlo);
    gemm_mask_kernel<<<256 + Nn / 8, 256, SMEM_GEMM>>>(adj);
    scores_kernel<<<Nn / 8, 256>>>(a);
    attn_mma_kernel<<<dim3(Hh, ITILES), 256, SMEM_ATTN>>>();
    colstats_kernel<<<OD / 32, 1024>>>();
    norm_relu_kernel<<<(Nn * OD / 8) / 256, 256>>>(gamma, beta, out);
}

// round 17
// speedup vs baseline: 1.0165x; 1.0165x over previous
#include <cuda_runtime.h>
#include <cuda_bf16.h>
#include <cuda_fp16.h>
#include <cstdint>

#define Nn 4096
#define IND 512
#define OD 512
#define Hh 8
#define Dd 64
#define ALPHA 0.2f
#define EPSV 1e-5f
#define LOG2E 1.4426950408889634f
#define ITILES 16
#define NTILES 32

__device__ __nv_bfloat16 g_xhi[Nn * IND], g_xlo[Nn * IND];
__device__ __nv_bfloat16 g_whi[OD * IND], g_wlo[OD * IND];
__device__ float g_Wh[Nn * OD];
__device__ __half g_Bf16[Nn * OD];                 // fp16(Wh), [i][o]
__device__ __half g_sdL[Hh * Nn], g_ssL[Hh * Nn];  // scores * log2(e), fp16
__device__ unsigned g_mask[Nn * (Nn / 32)];
__device__ float g_hp[Nn * OD];
__device__ float g_cs[ITILES * OD], g_cq[ITILES * OD];
__device__ float g_mean[OD], g_rstd[OD];

__device__ __forceinline__ unsigned bfpack(float hi, float lo) {
    unsigned r;
    asm("cvt.rn.bf16x2.f32 %0, %1, %2;" : "=r"(r) : "f"(hi), "f"(lo));
    return r;
}
__device__ __forceinline__ float lowf(unsigned u) { return __uint_as_float(u << 16); }
__device__ __forceinline__ float hif(unsigned u) { return __uint_as_float(u & 0xffff0000u); }
__device__ __forceinline__ uint32_t smem_u32(const void* p) {
    uint32_t a;
    asm("{ .reg .u64 t; cvta.to.shared.u64 t, %1; cvt.u32.u64 %0, t; }" : "=r"(a) : "l"(p));
    return a;
}
__device__ __forceinline__ unsigned hpack2n(float vlo, float vhi) {
    __half2 h = __floats2half2_rn(vlo, vhi);
    return reinterpret_cast<unsigned&>(h);
}
// half2 P chain: p2 = mask2 & ex2(max(t, alpha*t)), t = sd2 + ss2
__device__ __forceinline__ unsigned pchain2(__half2 sd2, __half2 ss2, __half2 alpha2,
                                            unsigned bits2) {
    __half2 t = __hadd2(sd2, ss2);
    __half2 g = __hmax2(t, __hmul2(t, alpha2));
    unsigned pe;
    asm("ex2.approx.f16x2 %0, %1;" : "=r"(pe) : "r"(reinterpret_cast<unsigned&>(g)));
    unsigned msk = ((bits2 & 1u) * 0xFFFFu) | (((bits2 >> 1) & 1u) * 0xFFFF0000u);
    return pe & msk;
}

#define MMA(cc, A0, A1, A2, A3, B0, B1)                                            \
    asm volatile("mma.sync.aligned.m16n8k16.row.col.f32.bf16.bf16.f32 "            \
                 "{%0,%1,%2,%3},{%4,%5,%6,%7},{%8,%9},{%0,%1,%2,%3};"              \
                 : "+f"(cc[0]), "+f"(cc[1]), "+f"(cc[2]), "+f"(cc[3])              \
                 : "r"(A0), "r"(A1), "r"(A2), "r"(A3), "r"(B0), "r"(B1))

#define MMA16(cc, A0, A1, A2, A3, B0, B1)                                          \
    asm volatile("mma.sync.aligned.m16n8k16.row.col.f32.f16.f16.f32 "              \
                 "{%0,%1,%2,%3},{%4,%5,%6,%7},{%8,%9},{%0,%1,%2,%3};"              \
                 : "+f"(cc[0]), "+f"(cc[1]), "+f"(cc[2]), "+f"(cc[3])              \
                 : "r"(A0), "r"(A1), "r"(A2), "r"(A3), "r"(B0), "r"(B1))

#define LDMX4T(r0, r1, r2, r3, addr)                                               \
    asm volatile("ldmatrix.sync.aligned.m8n8.x4.trans.shared.b16 {%0,%1,%2,%3},[%4];" \
                 : "=r"(r0), "=r"(r1), "=r"(r2), "=r"(r3) : "r"(addr))

#define LDMX4(r0, r1, r2, r3, addr)                                                \
    asm volatile("ldmatrix.sync.aligned.m8n8.x4.shared.b16 {%0,%1,%2,%3},[%4];"    \
                 : "=r"(r0), "=r"(r1), "=r"(r2), "=r"(r3) : "r"(addr))

#define CPA16(dst, src)                                                            \
    asm volatile("cp.async.cg.shared.global [%0], [%1], 16;" :: "r"(dst), "l"(src) : "memory")
#define CPCOMMIT() asm volatile("cp.async.commit_group;" ::: "memory")
#define CPWAIT(N) asm volatile("cp.async.wait_group %0;" :: "n"(N) : "memory")

// ================= Kernel P: fp32 -> bf16 hi/lo convert =================
__global__ void __launch_bounds__(256) cvt_kernel(const float* __restrict__ src,
                                                  __nv_bfloat16* __restrict__ hi,
                                                  __nv_bfloat16* __restrict__ lo) {
    const int i4 = (blockIdx.x * 256 + threadIdx.x) * 4;
    float4 v = *(const float4*)&src[i4];
    unsigned h01 = bfpack(v.y, v.x), h23 = bfpack(v.w, v.z);
    unsigned l01 = bfpack(v.y - hif(h01), v.x - lowf(h01));
    unsigned l23 = bfpack(v.w - hif(h23), v.z - lowf(h23));
    *(uint2*)&hi[i4] = make_uint2(h01, h23);
    *(uint2*)&lo[i4] = make_uint2(l01, l23);
}

// ================= Kernel A: Wh = x @ W^T via HMMA (bf16 3-MMA), double-buffered =================
#define GXHI 0
#define GXLO 16384
#define GWHI 32768
#define GWLO 40960
#define GBUF 49152
#define SMEM_GEMM (2 * GBUF)

__device__ __forceinline__ void gemm_issue(uint32_t smb, int buf, int i0, int o0, int k0, int t) {
    const uint32_t bb = smb + (unsigned)buf * GBUF;
#pragma unroll
    for (int q = 0; q < 4; q++) {
        int idx = t + q * 256;
        int i = idx >> 3, cc = idx & 7;
        unsigned so = (unsigned)i * 128u + (unsigned)((cc ^ (i & 7)) << 4);
        const size_t gof = (size_t)(i0 + i) * IND + k0 + cc * 8;
        CPA16(bb + GXHI + so, &g_xhi[gof]);
        CPA16(bb + GXLO + so, &g_xlo[gof]);
    }
#pragma unroll
    for (int q = 0; q < 2; q++) {
        int idx = t + q * 256;
        int o = idx >> 3, cc = idx & 7;
        unsigned so = (unsigned)o * 128u + (unsigned)((cc ^ (o & 7)) << 4);
        const size_t gof = (size_t)(o0 + o) * IND + k0 + cc * 8;
        CPA16(bb + GWHI + so, &g_whi[gof]);
        CPA16(bb + GWLO + so, &g_wlo[gof]);
    }
}

__global__ void __launch_bounds__(256, 2) gemm_mma_kernel() {
    extern __shared__ char dsm[];
    const uint32_t smb = smem_u32(dsm);
    const int o0 = blockIdx.x * 64, i0 = blockIdx.y * 128;
    const int t = threadIdx.x, w = t >> 5, lane = t & 31;
    const int l3 = lane & 3, l7 = lane & 7, l15 = lane & 15;

    float c[8][4];
#pragma unroll
    for (int nt = 0; nt < 8; nt++)
#pragma unroll
        for (int q = 0; q < 4; q++) c[nt][q] = 0.f;

    gemm_issue(smb, 0, i0, o0, 0, t);
    CPCOMMIT();

    for (int ch = 0; ch < 8; ch++) {
        if (ch < 7) {
            gemm_issue(smb, (ch + 1) & 1, i0, o0, (ch + 1) * 64, t);
            CPCOMMIT();
            CPWAIT(1);
        } else {
            CPWAIT(0);
        }
        __syncthreads();
        const uint32_t bb = smb + (unsigned)(ch & 1) * GBUF;

#pragma unroll
        for (int ks = 0; ks < 4; ks++) {
            uint32_t arow = bb + GXHI + (unsigned)(w * 16 + l15) * 128u +
                            (((unsigned)(2 * ks + (lane >> 4)) ^ (unsigned)l7) << 4);
            uint32_t ah0, ah1, ah2, ah3, al0, al1, al2, al3;
            LDMX4(ah0, ah1, ah2, ah3, arow);
            LDMX4(al0, al1, al2, al3, arow + 16384);
#pragma unroll
            for (int np = 0; np < 4; np++) {
                uint32_t brow = bb + GWHI +
                                (unsigned)(np * 16 + (lane >> 4) * 8 + l7) * 128u +
                                (((unsigned)(2 * ks + ((lane >> 3) & 1)) ^ (unsigned)l7) << 4);
                uint32_t bh0, bh1, bh2, bh3, bl0, bl1, bl2, bl3;
                LDMX4(bh0, bh1, bh2, bh3, brow);
                LDMX4(bl0, bl1, bl2, bl3, brow + 8192);
                MMA(c[2 * np], ah0, ah1, ah2, ah3, bh0, bh1);
                MMA(c[2 * np], al0, al1, al2, al3, bh0, bh1);
                MMA(c[2 * np], ah0, ah1, ah2, ah3, bl0, bl1);
                MMA(c[2 * np + 1], ah0, ah1, ah2, ah3, bh2, bh3);
                MMA(c[2 * np + 1], al0, al1, al2, al3, bh2, bh3);
                MMA(c[2 * np + 1], ah0, ah1, ah2, ah3, bl2, bl3);
            }
        }
        __syncthreads();
    }

    const int rA0 = w * 16 + (lane >> 2), rA1 = rA0 + 8;
#pragma unroll
    for (int nt = 0; nt < 8; nt++) {
        const int col = o0 + nt * 8 + l3 * 2;
        const size_t f0 = (size_t)(i0 + rA0) * OD + col;
        const size_t f1 = (size_t)(i0 + rA1) * OD + col;
        float v00 = c[nt][0], v01 = c[nt][1], v10 = c[nt][2], v11 = c[nt][3];
        *(float2*)&g_Wh[f0] = make_float2(v00, v01);
        *(float2*)&g_Wh[f1] = make_float2(v10, v11);
        *(unsigned*)&g_Bf16[f0] = hpack2n(v00, v01);
        *(unsigned*)&g_Bf16[f1] = hpack2n(v10, v11);
    }
}

// ================= Kernel B: adj -> bitmask (proven layout) =================
__global__ void __launch_bounds__(256) maskpack_kernel(const int* __restrict__ adj) {
    const int row = blockIdx.x;
    const int w = threadIdx.x >> 5, lane = threadIdx.x & 31;
    const int* arow = adj + (size_t)row * Nn;
#pragma unroll
    for (int k = 0; k < 16; k++) {
        int word = w * 16 + k;
        unsigned bal = __ballot_sync(0xffffffffu, arow[word * 32 + lane] > 0);
        if (lane == 0) g_mask[row * 128 + word] = bal;
    }
}

// ================= Kernel C: scores, warp-per-node, fp16 output =================
__global__ void __launch_bounds__(256) scores_kernel(const float* __restrict__ a) {
    const int w = threadIdx.x >> 5, lane = threadIdx.x & 31;
    const int j = blockIdx.x * 8 + w;
    const int h = lane >> 2, q = lane & 3;
    const float* wrow = &g_Wh[(size_t)j * OD + h * 64 + q * 16];
    float ss = 0.f, sd = 0.f;
#pragma unroll
    for (int d4 = 0; d4 < 4; d4++) {
        float4 wv = ((const float4*)wrow)[d4];
        float4 as = *(const float4*)&a[q * 16 + d4 * 4];
        float4 ad = *(const float4*)&a[64 + q * 16 + d4 * 4];
        ss += wv.x * as.x + wv.y * as.y + wv.z * as.z + wv.w * as.w;
        sd += wv.x * ad.x + wv.y * ad.y + wv.z * ad.z + wv.w * ad.w;
    }
    ss += __shfl_xor_sync(0xffffffffu, ss, 1);
    ss += __shfl_xor_sync(0xffffffffu, ss, 2);
    sd += __shfl_xor_sync(0xffffffffu, sd, 1);
    sd += __shfl_xor_sync(0xffffffffu, sd, 2);
    if (q == 0) {
        g_ssL[h * Nn + j] = __float2half(ss * LOG2E);
        g_sdL[h * Nn + j] = __float2half(sd * LOG2E);
    }
}

// ================= Kernel D: fp16 1-MMA attention, half2 P-phase =================
#define MSK_O 16384
#define SSL_O 20480
#define BUFSZ 21504
#define COLS_O 43008
#define COLQ_O 45056
#define SMEM_ATTN 47104

struct PFrag {
    unsigned a0, a1, a2, a3;
};

__device__ __forceinline__ PFrag make_frag(const char* bpd, int kk, int r0, int r1,
                                           __half2 sd2_0, __half2 sd2_1, __half2 alpha2,
                                           int l3, float& z0, float& z1) {
    const int jc = kk * 16 + l3 * 2;
    const __half2 sA = *(const __half2*)(bpd + SSL_O + jc * 2);
    const __half2 sB = *(const __half2*)(bpd + SSL_O + (jc + 8) * 2);
    const unsigned sh = (kk & 1) * 16 + l3 * 2;
    const unsigned mw0 = (*(const unsigned*)(bpd + MSK_O + r0 * 16 + ((kk >> 1) << 2))) >> sh;
    const unsigned mw1 = (*(const unsigned*)(bpd + MSK_O + r1 * 16 + ((kk >> 1) << 2))) >> sh;

    PFrag f;
    f.a0 = pchain2(sd2_0, sA, alpha2, mw0 & 3u);
    f.a2 = pchain2(sd2_0, sB, alpha2, (mw0 >> 8) & 3u);
    f.a1 = pchain2(sd2_1, sA, alpha2, mw1 & 3u);
    f.a3 = pchain2(sd2_1, sB, alpha2, (mw1 >> 8) & 3u);

    __half2 s0 = __hadd2(reinterpret_cast<const __half2&>(f.a0),
                         reinterpret_cast<const __half2&>(f.a2));
    __half2 s1 = __hadd2(reinterpret_cast<const __half2&>(f.a1),
                         reinterpret_cast<const __half2&>(f.a3));
    float2 f20 = __half22float2(s0);
    float2 f21 = __half22float2(s1);
    z0 += f20.x + f20.y;
    z1 += f21.x + f21.y;
    return f;
}

__device__ __forceinline__ void attn_issue(uint32_t smb, int b, int h, int i0, int j0, int t) {
    const uint32_t bb = smb + (unsigned)b * BUFSZ;
#pragma unroll
    for (int q = 0; q < 4; q++) {
        int idx = t + q * 256;
        int j = idx >> 3, cc = idx & 7;
        unsigned so = (unsigned)j * 128u + (unsigned)((cc ^ (j & 7)) << 4);
        CPA16(bb + so, &g_Bf16[(size_t)(j0 + j) * OD + h * 64 + cc * 8]);
    }
    CPA16(bb + MSK_O + t * 16, &g_mask[(size_t)(i0 + t) * 128 + (j0 >> 5)]);
    if (t < 16) CPA16(bb + SSL_O + t * 16, &g_ssL[h * Nn + j0 + t * 8]);
}

__global__ void __launch_bounds__(256, 1) attn_mma_kernel() {
    extern __shared__ char dsm[];
    const uint32_t smb = smem_u32(dsm);

    const int h = blockIdx.x, it = blockIdx.y, i0 = it * 256;
    const int t = threadIdx.x, w = t >> 5, lane = t & 31;
    const int l3 = lane & 3, l7 = lane & 7, l15 = lane & 15;
    const int rB = w * 32 + (lane >> 2);
    const __half2 alpha2 = __floats2half2_rn(ALPHA, ALPHA);
    const __half2 sd2_0 = __half2half2(g_sdL[h * Nn + i0 + rB]);
    const __half2 sd2_1 = __half2half2(g_sdL[h * Nn + i0 + rB + 8]);
    const __half2 sd2_2 = __half2half2(g_sdL[h * Nn + i0 + rB + 16]);
    const __half2 sd2_3 = __half2half2(g_sdL[h * Nn + i0 + rB + 24]);

    float z0 = 0.f, z1 = 0.f, z2 = 0.f, z3 = 0.f;
    float c[2][8][4];
#pragma unroll
    for (int blk = 0; blk < 2; blk++)
#pragma unroll
        for (int nt = 0; nt < 8; nt++)
#pragma unroll
            for (int q = 0; q < 4; q++) c[blk][nt][q] = 0.f;

    attn_issue(smb, 0, h, i0, 0, t);
    CPCOMMIT();

    for (int tl = 0; tl < NTILES; tl++) {
        if (tl < NTILES - 1) {
            attn_issue(smb, (tl + 1) & 1, h, i0, (tl + 1) * 128, t);
            CPCOMMIT();
            CPWAIT(1);
        } else {
            CPWAIT(0);
        }
        __syncthreads();

        const uint32_t bb = smb + (unsigned)(tl & 1) * BUFSZ;
        const char* bpd = dsm + (tl & 1) * BUFSZ;

#pragma unroll
        for (int kk = 0; kk < 8; kk++) {
            PFrag f0 = make_frag(bpd, kk, rB, rB + 8, sd2_0, sd2_1, alpha2, l3, z0, z1);
            PFrag f1 = make_frag(bpd, kk, rB + 16, rB + 24, sd2_2, sd2_3, alpha2, l3, z2, z3);

            const unsigned rowoff = (unsigned)(kk * 16 + l15) * 128u;
#pragma unroll
            for (int np = 0; np < 4; np++) {
                const unsigned chn =
                    (((unsigned)(np * 2 + (lane >> 4)) ^ (unsigned)l7) << 4);
                uint32_t bh0, bh1, bh2, bh3;
                LDMX4T(bh0, bh1, bh2, bh3, bb + rowoff + chn);
                MMA16(c[0][2 * np], f0.a0, f0.a1, f0.a2, f0.a3, bh0, bh1);
                MMA16(c[1][2 * np], f1.a0, f1.a1, f1.a2, f1.a3, bh0, bh1);
                MMA16(c[0][2 * np + 1], f0.a0, f0.a1, f0.a2, f0.a3, bh2, bh3);
                MMA16(c[1][2 * np + 1], f1.a0, f1.a1, f1.a2, f1.a3, bh2, bh3);
            }
        }
        __syncthreads();
    }

#pragma unroll
    for (int d = 1; d <= 2; d <<= 1) {
        z0 += __shfl_xor_sync(0xffffffffu, z0, d);
        z1 += __shfl_xor_sync(0xffffffffu, z1, d);
        z2 += __shfl_xor_sync(0xffffffffu, z2, d);
        z3 += __shfl_xor_sync(0xffffffffu, z3, d);
    }
    const float inv[4] = {1.0f / z0, 1.0f / z1, 1.0f / z2, 1.0f / z3};

    float* colS = (float*)(dsm + COLS_O);
    float* colQ = (float*)(dsm + COLQ_O);

#pragma unroll
    for (int nt = 0; nt < 8; nt++) {
        float vv[4][2];
#pragma unroll
        for (int blk = 0; blk < 2; blk++) {
#pragma unroll
            for (int half = 0; half < 2; half++) {
                const int ri = blk * 2 + half;
                float va = c[blk][nt][2 * half] * inv[ri];
                float vb = c[blk][nt][2 * half + 1] * inv[ri];
                vv[ri][0] = va;
                vv[ri][1] = vb;
                const int row = rB + blk * 16 + half * 8;
                *(float2*)&g_hp[(size_t)(i0 + row) * OD + h * 64 + nt * 8 + l3 * 2] =
                    make_float2(va, vb);
            }
        }
        float s0 = vv[0][0] + vv[1][0] + vv[2][0] + vv[3][0];
        float s1 = vv[0][1] + vv[1][1] + vv[2][1] + vv[3][1];
        float q0 = vv[0][0] * vv[0][0] + vv[1][0] * vv[1][0] + vv[2][0] * vv[2][0] +
                   vv[3][0] * vv[3][0];
        float q1 = vv[0][1] * vv[0][1] + vv[1][1] * vv[1][1] + vv[2][1] * vv[2][1] +
                   vv[3][1] * vv[3][1];
#pragma unroll
        for (int d = 4; d < 32; d <<= 1) {
            s0 += __shfl_xor_sync(0xffffffffu, s0, d);
            s1 += __shfl_xor_sync(0xffffffffu, s1, d);
            q0 += __shfl_xor_sync(0xffffffffu, q0, d);
            q1 += __shfl_xor_sync(0xffffffffu, q1, d);
        }
        if (lane < 4) {
            colS[w * 64 + nt * 8 + lane * 2] = s0;
            colS[w * 64 + nt * 8 + lane * 2 + 1] = s1;
            colQ[w * 64 + nt * 8 + lane * 2] = q0;
            colQ[w * 64 + nt * 8 + lane * 2 + 1] = q1;
        }
    }
    __syncthreads();
    if (t < 64) {
        float s = 0.f, q = 0.f;
#pragma unroll
        for (int ww = 0; ww < 8; ww++) {
            s += colS[ww * 64 + t];
            q += colQ[ww * 64 + t];
        }
        g_cs[it * OD + h * 64 + t] = s;
        g_cq[it * OD + h * 64 + t] = q;
    }
}

// ================= Kernel E: column stats =================
__global__ void __launch_bounds__(1024) colstats_kernel() {
    const int w = threadIdx.x >> 5, lane = threadIdx.x & 31;
    const int col = blockIdx.x * 32 + w;
    float s = (lane < ITILES) ? g_cs[lane * OD + col] : 0.f;
    float q = (lane < ITILES) ? g_cq[lane * OD + col] : 0.f;
#pragma unroll
    for (int d = 16; d >= 1; d >>= 1) {
        s += __shfl_xor_sync(0xffffffffu, s, d);
        q += __shfl_xor_sync(0xffffffffu, q, d);
    }
    if (lane == 0) {
        float mean = s * (1.0f / Nn);
        float var = q * (1.0f / Nn) - mean * mean;
        g_mean[col] = mean;
        g_rstd[col] = rsqrtf(var + EPSV);
    }
}

// ================= Kernel F: layernorm + relu =================
__global__ void __launch_bounds__(256) norm_relu_kernel(const float* __restrict__ gamma,
                                                        const float* __restrict__ beta,
                                                        float* __restrict__ out) {
    const int base8 = (blockIdx.x * 256 + threadIdx.x) * 8;
#pragma unroll
    for (int half = 0; half < 2; half++) {
        const int basei = base8 + half * 4;
        const int col = basei & (OD - 1);
        float4 xv = *(const float4*)&g_hp[basei];
        float4 mn = *(const float4*)&g_mean[col];
        float4 rs = *(const float4*)&g_rstd[col];
        float4 ga = *(const float4*)&gamma[col];
        float4 be = *(const float4*)&beta[col];
        float4 o;
        o.x = fmaxf(0.f, ga.x * (xv.x - mn.x) * rs.x + be.x);
        o.y = fmaxf(0.f, ga.y * (xv.y - mn.y) * rs.y + be.y);
        o.z = fmaxf(0.f, ga.z * (xv.z - mn.z) * rs.z + be.z);
        o.w = fmaxf(0.f, ga.w * (xv.w - mn.w) * rs.w + be.w);
        *(float4*)&out[basei] = o;
    }
}

// ================= launch =================
extern "C" void kernel_launch(void* const* d_in, const int* in_sizes, int n_in,
                              void* d_out, int out_size) {
    const float* x     = (const float*)d_in[0];
    const int*   adj   = (const int*)d_in[1];
    const float* W     = (const float*)d_in[2];
    const float* a     = (const float*)d_in[3];
    const float* gamma = (const float*)d_in[4];
    const float* beta  = (const float*)d_in[5];
    float* out = (float*)d_out;

    static int attrs_set = 0;
    if (!attrs_set) {
        cudaFuncSetAttribute(attn_mma_kernel,
                             cudaFuncAttributeMaxDynamicSharedMemorySize, SMEM_ATTN);
        cudaFuncSetAttribute(gemm_mma_kernel,
                             cudaFuncAttributeMaxDynamicSharedMemorySize, SMEM_GEMM);
        attrs_set = 1;
    }

    __nv_bfloat16 *xhi, *xlo, *whi, *wlo;
    cudaGetSymbolAddress((void**)&xhi, g_xhi);
    cudaGetSymbolAddress((void**)&xlo, g_xlo);
    cudaGetSymbolAddress((void**)&whi, g_whi);
    cudaGetSymbolAddress((void**)&wlo, g_wlo);

    cvt_kernel<<<(Nn * IND / 4) / 256, 256>>>(x, xhi, xlo);
    cvt_kernel<<<(OD * IND / 4) / 256, 256>>>(W, whi, wlo);
    gemm_mma_kernel<<<dim3(OD / 64, Nn / 128), 256, SMEM_GEMM>>>();
    scores_kernel<<<Nn / 8, 256>>>(a);
    maskpack_kernel<<<Nn, 256>>>(adj);
    attn_mma_kernel<<<dim3(Hh, ITILES), 256, SMEM_ATTN>>>();
    colstats_kernel<<<OD / 32, 1024>>>();
    norm_relu_kernel<<<(Nn * OD / 8) / 256, 256>>>(gamma, beta, out);
}